// round 9
// baseline (speedup 1.0000x reference)
#include <cuda_runtime.h>
#include <cuda_bf16.h>
#include <cstdint>

// Problem constants
#define BB 2048
#define SS 512
#define DD 128
#define HH 64
#define OO 8
#define H4 16
#define EPSF 1e-5f

typedef unsigned long long u64;

#define DI __device__ __forceinline__

DI u64 pk2(float lo, float hi) {
    u64 r; asm("mov.b64 %0, {%1, %2};" : "=l"(r) : "f"(lo), "f"(hi)); return r;
}
DI void upk2(u64 v, float& lo, float& hi) {
    asm("mov.b64 {%0, %1}, %2;" : "=f"(lo), "=f"(hi) : "l"(v));
}
DI u64 ffma2(u64 a, u64 b, u64 c) {
    u64 d; asm("fma.rn.f32x2 %0, %1, %2, %3;" : "=l"(d) : "l"(a), "l"(b), "l"(c)); return d;
}

// ---- device scratch (static; runtime alloc is forbidden) ----
// xp layout: float4 at index ((b*128 + s4)*64 + h), component j = timestep 4*s4+j
__device__ __align__(16) float g_xp[(size_t)SS * BB * HH];   // 256 MB
__device__ __align__(16) float g_z1[BB * H4];
__device__ float g_bn1a[HH], g_bn1c[HH];
__device__ float g_part[16][2][H4];

// =====================================================================
// K1: projection. Warp task = (b, s4, feature-half): 4 consecutive
// timesteps x 32 features. W_ih rows in registers (64 f32x2); x rows
// broadcast from SMEM via LDS.128. Output: one coalesced float4/lane.
// Note x row base for task t is simply x + t*512 (4 rows of 128 floats),
// and the output float4 index is t*64 + i.
// =====================================================================
__global__ void __launch_bounds__(128, 3) k_proj(
    const float* __restrict__ x, const float* __restrict__ Wih,
    const float* __restrict__ bih, const float* __restrict__ bhh)
{
    __shared__ __align__(16) float sx[4][4][DD];   // [warp][row j][128]
    const int lane = threadIdx.x & 31;
    const int warp = threadIdx.x >> 5;
    const int gw   = blockIdx.x * 4 + warp;
    const int NW   = gridDim.x * 4;
    const int half = gw & 1;
    const int i    = half * 32 + lane;

    // W_ih row i into registers as 64 packed f32x2
    u64 w[64];
    const ulonglong2* wp = (const ulonglong2*)(Wih + (size_t)i * DD);
#pragma unroll
    for (int k = 0; k < 32; k++) { ulonglong2 t2 = wp[k]; w[2*k] = t2.x; w[2*k+1] = t2.y; }
    const float bias = bih[i] + bhh[i];

    const unsigned NT   = BB * (SS / 4);       // 262144 tasks
    const unsigned TSTR = (unsigned)(NW >> 1);
    unsigned t = (unsigned)(gw >> 1);
    if (t >= NT) return;

    // prefetch first task's 4 x-rows (2KB contiguous)
    float4 xv0, xv1, xv2, xv3;
    {
        const float4* xp4 = (const float4*)(x + (size_t)t * 512);
        xv0 = xp4[lane]; xv1 = xp4[32 + lane]; xv2 = xp4[64 + lane]; xv3 = xp4[96 + lane];
    }
    float4* outp = (float4*)g_xp;

    for (; t < NT; t += TSTR) {
        *(float4*)&sx[warp][0][lane * 4] = xv0;
        *(float4*)&sx[warp][1][lane * 4] = xv1;
        *(float4*)&sx[warp][2][lane * 4] = xv2;
        *(float4*)&sx[warp][3][lane * 4] = xv3;
        __syncwarp();

        unsigned tn = t + TSTR;
        if (tn < NT) {
            const float4* xp4 = (const float4*)(x + (size_t)tn * 512);
            xv0 = xp4[lane]; xv1 = xp4[32 + lane]; xv2 = xp4[64 + lane]; xv3 = xp4[96 + lane];
        }

        float v[4];
#pragma unroll
        for (int j = 0; j < 4; j++) {
            const ulonglong2* sp = (const ulonglong2*)sx[warp][j];
            u64 a0 = 0, a1 = 0;
#pragma unroll
            for (int k = 0; k < 32; k++) {
                ulonglong2 p = sp[k];
                a0 = ffma2(w[2*k],     p.x, a0);
                a1 = ffma2(w[2*k + 1], p.y, a1);
            }
            float l0, h0, l1, h1;
            upk2(a0, l0, h0); upk2(a1, l1, h1);
            v[j] = (l0 + h0) + (l1 + h1) + bias;
        }
        __syncwarp();

        outp[(size_t)t * 64 + i] = make_float4(v[0], v[1], v[2], v[3]);
    }
}

// =====================================================================
// K2: recurrence. Warp owns 2 batch rows; lane owns features (lane,
// lane+32) for both. W_hh rows in regs. h double-buffered in SMEM
// (LDS.128 broadcast). xp read as float4 = 4 timesteps, prefetched one
// GROUP (4 steps, ~1800 cyc) ahead -> DRAM latency hidden.
// =====================================================================
__global__ void __launch_bounds__(128, 2) k_rnn(
    const float* __restrict__ h0, const float* __restrict__ Whh,
    float* __restrict__ dout)
{
    __shared__ __align__(16) float sh[4][2][2][HH];  // [warp][row][buf][64]
    const int lane = threadIdx.x & 31;
    const int warp = threadIdx.x >> 5;
    const int gw   = blockIdx.x * 4 + warp;          // 0..1023
    const int b0   = gw * 2;
    const int b1   = gw * 2 + 1;

    u64 w0[32], w1[32];
    {
        const ulonglong2* p0 = (const ulonglong2*)(Whh + (size_t)lane * HH);
        const ulonglong2* p1 = (const ulonglong2*)(Whh + (size_t)(lane + 32) * HH);
#pragma unroll
        for (int k = 0; k < 16; k++) {
            ulonglong2 a = p0[k]; w0[2*k] = a.x; w0[2*k+1] = a.y;
            ulonglong2 b = p1[k]; w1[2*k] = b.x; w1[2*k+1] = b.y;
        }
    }

    float (*shw)[2][HH] = sh[warp];
    shw[0][0][lane]      = h0[(size_t)b0 * HH + lane];
    shw[0][0][lane + 32] = h0[(size_t)b0 * HH + lane + 32];
    shw[1][0][lane]      = h0[(size_t)b1 * HH + lane];
    shw[1][0][lane + 32] = h0[(size_t)b1 * HH + lane + 32];
    __syncwarp();

    const float4* xp4 = (const float4*)g_xp;
    const size_t base0 = (size_t)b0 * 128 * 64;
    const size_t base1 = (size_t)b1 * 128 * 64;

    // prefetch group 0
    float4 c00 = xp4[base0 + lane];
    float4 c01 = xp4[base0 + lane + 32];
    float4 c10 = xp4[base1 + lane];
    float4 c11 = xp4[base1 + lane + 32];

    int buf = 0;
    float v00 = 0.f, v01 = 0.f, v10 = 0.f, v11 = 0.f;

    for (int g = 0; g < 128; g++) {
        float4 n00 = {0,0,0,0}, n01 = {0,0,0,0}, n10 = {0,0,0,0}, n11 = {0,0,0,0};
        if (g + 1 < 128) {
            size_t o0 = base0 + (size_t)(g + 1) * 64;
            size_t o1 = base1 + (size_t)(g + 1) * 64;
            n00 = xp4[o0 + lane]; n01 = xp4[o0 + lane + 32];
            n10 = xp4[o1 + lane]; n11 = xp4[o1 + lane + 32];
        }

#pragma unroll
        for (int j = 0; j < 4; j++) {
            const ulonglong2* hp0 = (const ulonglong2*)shw[0][buf];
            const ulonglong2* hp1 = (const ulonglong2*)shw[1][buf];
            u64 a00 = 0, a01 = 0, a10 = 0, a11 = 0;
#pragma unroll
            for (int k = 0; k < 16; k++) {
                ulonglong2 q0 = hp0[k];
                ulonglong2 q1 = hp1[k];
                a00 = ffma2(w0[2*k], q0.x, a00); a00 = ffma2(w0[2*k+1], q0.y, a00);
                a01 = ffma2(w1[2*k], q0.x, a01); a01 = ffma2(w1[2*k+1], q0.y, a01);
                a10 = ffma2(w0[2*k], q1.x, a10); a10 = ffma2(w0[2*k+1], q1.y, a10);
                a11 = ffma2(w1[2*k], q1.x, a11); a11 = ffma2(w1[2*k+1], q1.y, a11);
            }
            const float px00 = (j == 0) ? c00.x : (j == 1) ? c00.y : (j == 2) ? c00.z : c00.w;
            const float px01 = (j == 0) ? c01.x : (j == 1) ? c01.y : (j == 2) ? c01.z : c01.w;
            const float px10 = (j == 0) ? c10.x : (j == 1) ? c10.y : (j == 2) ? c10.z : c10.w;
            const float px11 = (j == 0) ? c11.x : (j == 1) ? c11.y : (j == 2) ? c11.z : c11.w;

            float lo, hi;
            upk2(a00, lo, hi); v00 = fmaxf(lo + hi + px00, 0.f);
            upk2(a01, lo, hi); v01 = fmaxf(lo + hi + px01, 0.f);
            upk2(a10, lo, hi); v10 = fmaxf(lo + hi + px10, 0.f);
            upk2(a11, lo, hi); v11 = fmaxf(lo + hi + px11, 0.f);

            buf ^= 1;
            shw[0][buf][lane]      = v00;
            shw[0][buf][lane + 32] = v01;
            shw[1][buf][lane]      = v10;
            shw[1][buf][lane + 32] = v11;
            __syncwarp();
        }
        c00 = n00; c01 = n01; c10 = n10; c11 = n11;
    }

    float* hT = dout + (size_t)BB * OO;
    hT[(size_t)b0 * HH + lane]      = v00;
    hT[(size_t)b0 * HH + lane + 32] = v01;
    hT[(size_t)b1 * HH + lane]      = v10;
    hT[(size_t)b1 * HH + lane + 32] = v11;
}

// =====================================================================
// K3: batchnorm-1 stats, one block per feature, shuffle reduction.
// =====================================================================
__global__ void k_bn1stats(const float* __restrict__ dout,
                           const float* __restrict__ g, const float* __restrict__ bb)
{
    const float* hT = dout + (size_t)BB * OO;
    const int f = blockIdx.x, t = threadIdx.x;
    float s = 0.f, q = 0.f;
    for (int b = t; b < BB; b += 128) {
        float v = hT[(size_t)b * HH + f];
        s += v; q += v * v;
    }
#pragma unroll
    for (int off = 16; off > 0; off >>= 1) {
        s += __shfl_xor_sync(0xffffffffu, s, off);
        q += __shfl_xor_sync(0xffffffffu, q, off);
    }
    __shared__ float ws[4], wq[4];
    if ((t & 31) == 0) { ws[t >> 5] = s; wq[t >> 5] = q; }
    __syncthreads();
    if (t == 0) {
        s = (ws[0] + ws[1]) + (ws[2] + ws[3]);
        q = (wq[0] + wq[1]) + (wq[2] + wq[3]);
        float mu  = s * (1.f / BB);
        float var = q * (1.f / BB) - mu * mu;
        float a   = g[f] * rsqrtf(var + EPSF);
        g_bn1a[f] = a;
        g_bn1c[f] = bb[f] - mu * a;
    }
}

// =====================================================================
// K4: z1 = relu(bn1(hT) @ fc1_W^T + b); per-block bn2 partial stats via
// shuffle reduction (1 barrier instead of 224). grid 16 x 128.
// =====================================================================
__global__ void k_fc1(const float* __restrict__ dout,
                      const float* __restrict__ W1, const float* __restrict__ b1f)
{
    const float* hT = dout + (size_t)BB * OO;
    __shared__ float sW[H4 * HH];
    __shared__ float sa[HH], sc[HH], sb[H4];
    __shared__ float wsum[4][H4], wsq[4][H4];
    const int t = threadIdx.x;
    const int lane = t & 31, warp = t >> 5;
    for (int i = t; i < H4 * HH; i += 128) sW[i] = W1[i];
    if (t < HH) { sa[t] = g_bn1a[t]; sc[t] = g_bn1c[t]; }
    if (t < H4) sb[t] = b1f[t];
    __syncthreads();

    const int b = blockIdx.x * 128 + t;
    float y[HH];
    {
        const float4* hp = (const float4*)(hT + (size_t)b * HH);
#pragma unroll
        for (int k = 0; k < 16; k++) {
            float4 u = hp[k];
            y[4*k]   = sa[4*k]   * u.x + sc[4*k];
            y[4*k+1] = sa[4*k+1] * u.y + sc[4*k+1];
            y[4*k+2] = sa[4*k+2] * u.z + sc[4*k+2];
            y[4*k+3] = sa[4*k+3] * u.w + sc[4*k+3];
        }
    }

    float s[H4], q[H4];
    float4* z4 = (float4*)(g_z1 + (size_t)b * H4);
#pragma unroll
    for (int j4 = 0; j4 < 4; j4++) {
        float4 zv;
        float* zp = (float*)&zv;
#pragma unroll
        for (int jj = 0; jj < 4; jj++) {
            int j = j4 * 4 + jj;
            float acc = sb[j];
#pragma unroll
            for (int f = 0; f < HH; f++) acc += sW[j * HH + f] * y[f];
            acc = fmaxf(acc, 0.f);
            zp[jj] = acc;
            s[j] = acc; q[j] = acc * acc;
        }
        z4[j4] = zv;
    }

#pragma unroll
    for (int j = 0; j < H4; j++) {
#pragma unroll
        for (int off = 16; off > 0; off >>= 1) {
            s[j] += __shfl_xor_sync(0xffffffffu, s[j], off);
            q[j] += __shfl_xor_sync(0xffffffffu, q[j], off);
        }
    }
    if (lane == 0) {
#pragma unroll
        for (int j = 0; j < H4; j++) { wsum[warp][j] = s[j]; wsq[warp][j] = q[j]; }
    }
    __syncthreads();
    if (t < H4) {
        g_part[blockIdx.x][0][t] = (wsum[0][t] + wsum[1][t]) + (wsum[2][t] + wsum[3][t]);
        g_part[blockIdx.x][1][t] = (wsq[0][t]  + wsq[1][t])  + (wsq[2][t]  + wsq[3][t]);
    }
}

// =====================================================================
// K5: out = bn2(z1) @ fc2_W^T + b, bn2 coefficients finalized in-block.
// grid 16 x 128.
// =====================================================================
__global__ void k_fc2(const float* __restrict__ g2, const float* __restrict__ b2,
                      const float* __restrict__ W2, const float* __restrict__ b2f,
                      float* __restrict__ out)
{
    __shared__ float sW[OO * H4], sa[H4], sc[H4], sb[OO];
    const int t = threadIdx.x;
    if (t < H4) {
        float s = 0.f, q = 0.f;
#pragma unroll
        for (int k = 0; k < 16; k++) { s += g_part[k][0][t]; q += g_part[k][1][t]; }
        float mu  = s * (1.f / BB);
        float var = q * (1.f / BB) - mu * mu;
        float a   = g2[t] * rsqrtf(var + EPSF);
        sa[t] = a;
        sc[t] = b2[t] - mu * a;
    }
    sW[t] = W2[t];                 // OO*H4 == 128 == blockDim
    if (t < OO) sb[t] = b2f[t];
    __syncthreads();

    const int b = blockIdx.x * 128 + t;
    float z[H4];
    {
        const float4* zp = (const float4*)(g_z1 + (size_t)b * H4);
#pragma unroll
        for (int k = 0; k < 4; k++) {
            float4 u = zp[k];
            z[4*k]   = sa[4*k]   * u.x + sc[4*k];
            z[4*k+1] = sa[4*k+1] * u.y + sc[4*k+1];
            z[4*k+2] = sa[4*k+2] * u.z + sc[4*k+2];
            z[4*k+3] = sa[4*k+3] * u.w + sc[4*k+3];
        }
    }
#pragma unroll
    for (int o = 0; o < OO; o++) {
        float acc = sb[o];
#pragma unroll
        for (int j = 0; j < H4; j++) acc += sW[o * H4 + j] * z[j];
        out[(size_t)b * OO + o] = acc;
    }
}

// =====================================================================
extern "C" void kernel_launch(void* const* d_in, const int* in_sizes, int n_in,
                              void* d_out, int out_size)
{
    const float* x    = (const float*)d_in[0];
    const float* h0   = (const float*)d_in[1];
    const float* Wih  = (const float*)d_in[2];
    const float* Whh  = (const float*)d_in[3];
    const float* bih  = (const float*)d_in[4];
    const float* bhh  = (const float*)d_in[5];
    const float* bn1g = (const float*)d_in[6];
    const float* bn1b = (const float*)d_in[7];
    const float* fc1W = (const float*)d_in[8];
    const float* fc1b = (const float*)d_in[9];
    const float* bn2g = (const float*)d_in[10];
    const float* bn2b = (const float*)d_in[11];
    const float* fc2W = (const float*)d_in[12];
    const float* fc2b = (const float*)d_in[13];
    float* out = (float*)d_out;

    cudaStream_t s0 = 0;
    k_proj<<<444, 128, 0, s0>>>(x, Wih, bih, bhh);
    k_rnn<<<256, 128, 0, s0>>>(h0, Whh, out);
    k_bn1stats<<<64, 128, 0, s0>>>(out, bn1g, bn1b);
    k_fc1<<<16, 128, 0, s0>>>(out, fc1W, fc1b);
    k_fc2<<<16, 128, 0, s0>>>(bn2g, bn2b, fc2W, fc2b, out);
}

// round 11
// speedup vs baseline: 2.0544x; 2.0544x over previous
#include <cuda_runtime.h>
#include <cuda_bf16.h>
#include <cstdint>

// Problem constants
#define BB 2048
#define SS 512
#define DD 128
#define HH 64
#define OO 8
#define H4 16
#define EPSF 1e-5f

typedef unsigned long long u64;
typedef unsigned int u32;

#define DI __device__ __forceinline__

DI void upk2(u64 v, float& lo, float& hi) {
    asm("mov.b64 {%0, %1}, %2;" : "=f"(lo), "=f"(hi) : "l"(v));
}
DI u64 ffma2(u64 a, u64 b, u64 c) {
    u64 d; asm("fma.rn.f32x2 %0, %1, %2, %3;" : "=l"(d) : "l"(a), "l"(b), "l"(c)); return d;
}

// ---- device scratch (static; runtime alloc is forbidden) ----
// xp layout: plain [row][64] fp32, row = b*512 + s   (GEMM output layout)
__device__ __align__(16) float g_xp[(size_t)SS * BB * HH];   // 256 MB
__device__ __align__(16) float g_z1[BB * H4];
__device__ float g_bn1a[HH], g_bn1c[HH];
__device__ float g_part[16][2][H4];

// ============ bf16 hi/lo split helpers =============================
// pack (even, odd) fp32 pair -> bf16x2 hi (low16 = even) and residual lo
DI void split2(float e, float o, u32& hi, u32& lo) {
    u32 h;
    asm("cvt.rn.bf16x2.f32 %0, %1, %2;" : "=r"(h) : "f"(o), "f"(e));
    float he = __uint_as_float(h << 16);
    float ho = __uint_as_float(h & 0xffff0000u);
    float re = e - he;
    float ro = o - ho;
    u32 l;
    asm("cvt.rn.bf16x2.f32 %0, %1, %2;" : "=r"(l) : "f"(ro), "f"(re));
    hi = h; lo = l;
}

// D = A(row) x B(col) + D,  m16n8k16 bf16 -> f32
DI void mma16816(float* c, const u32* a, const u32* b) {
    asm("mma.sync.aligned.m16n8k16.row.col.f32.bf16.bf16.f32 "
        "{%0,%1,%2,%3}, {%4,%5,%6,%7}, {%8,%9}, {%0,%1,%2,%3};"
        : "+f"(c[0]), "+f"(c[1]), "+f"(c[2]), "+f"(c[3])
        : "r"(a[0]), "r"(a[1]), "r"(a[2]), "r"(a[3]), "r"(b[0]), "r"(b[1]));
}

// =====================================================================
// K1: projection via warp-level bf16 split MMA.
// out[row][n] = sum_k x[row][k] * W_ih[n][k] + bias[n]
// Warp-task = 16 rows x 32 outputs (n-half by warp parity), K=128.
// A fragments loaded straight from GMEM into lane-register positions,
// split hi/lo in registers. B (W_ih) fragments register-resident.
// 3 MMAs per (ntile, kstep): hh + hl + lh.  No SMEM, no syncs.
// =====================================================================
#define NRT ((BB * SS) / 16)     // 65536 row-tiles
#define PROJ_BLOCKS 296          // 2 CTAs/SM, 1184 warps

__global__ void __launch_bounds__(128, 2) k_proj(
    const float* __restrict__ x, const float* __restrict__ Wih,
    const float* __restrict__ bih, const float* __restrict__ bhh)
{
    const int lane  = threadIdx.x & 31;
    const int warp  = threadIdx.x >> 5;
    const int gw    = blockIdx.x * 4 + warp;        // 0..1183
    const int nhalf = gw & 1;
    const int nbase = nhalf * 32;
    const int l4    = lane & 3;        // pair-column group
    const int lr    = lane >> 2;       // row-in-frag / n-in-frag

    // ---- B fragments: W_ih hi/lo, register resident ----
    u32 bh[4][8][2], bl[4][8][2];
#pragma unroll
    for (int nt = 0; nt < 4; nt++) {
        const int n = nbase + nt * 8 + lr;
        const float* wr = Wih + (size_t)n * DD;
#pragma unroll
        for (int ks = 0; ks < 8; ks++) {
            const int k = ks * 16 + l4 * 2;
            float2 q0 = *(const float2*)(wr + k);
            float2 q1 = *(const float2*)(wr + k + 8);
            split2(q0.x, q0.y, bh[nt][ks][0], bl[nt][ks][0]);
            split2(q1.x, q1.y, bh[nt][ks][1], bl[nt][ks][1]);
        }
    }

    // ---- bias per lane-column ----
    float bc[4][2];
#pragma unroll
    for (int nt = 0; nt < 4; nt++) {
        const int col = nbase + nt * 8 + l4 * 2;
        bc[nt][0] = bih[col]     + bhh[col];
        bc[nt][1] = bih[col + 1] + bhh[col + 1];
    }

    // ---- persistent loop over row-tiles ----
    for (u32 rt = (u32)(gw >> 1); rt < NRT; rt += 592u) {
        const float* xr = x + ((size_t)rt * 16 + lr) * DD + l4 * 2;

        float c[4][4];
#pragma unroll
        for (int nt = 0; nt < 4; nt++) {
            c[nt][0] = bc[nt][0]; c[nt][1] = bc[nt][1];
            c[nt][2] = bc[nt][0]; c[nt][3] = bc[nt][1];
        }

        // one-deep kstep pipeline
        float2 P0 = *(const float2*)(xr);
        float2 P1 = *(const float2*)(xr + 8 * DD);
        float2 P2 = *(const float2*)(xr + 8);
        float2 P3 = *(const float2*)(xr + 8 * DD + 8);

#pragma unroll
        for (int ks = 0; ks < 8; ks++) {
            float2 N0, N1, N2, N3;
            if (ks < 7) {
                const float* xn = xr + (ks + 1) * 16;
                N0 = *(const float2*)(xn);
                N1 = *(const float2*)(xn + 8 * DD);
                N2 = *(const float2*)(xn + 8);
                N3 = *(const float2*)(xn + 8 * DD + 8);
            }
            u32 ah[4], al[4];
            split2(P0.x, P0.y, ah[0], al[0]);
            split2(P1.x, P1.y, ah[1], al[1]);
            split2(P2.x, P2.y, ah[2], al[2]);
            split2(P3.x, P3.y, ah[3], al[3]);

#pragma unroll
            for (int nt = 0; nt < 4; nt++) {
                mma16816(c[nt], ah, bh[nt][ks]);
                mma16816(c[nt], ah, bl[nt][ks]);
                mma16816(c[nt], al, bh[nt][ks]);
            }
            if (ks < 7) { P0 = N0; P1 = N1; P2 = N2; P3 = N3; }
        }

        // epilogue: rows rt*16+lr and +8, cols nbase + nt*8 + l4*2
        float* o0 = g_xp + ((size_t)rt * 16 + lr) * HH + nbase + l4 * 2;
        float* o1 = o0 + 8 * HH;
#pragma unroll
        for (int nt = 0; nt < 4; nt++) {
            *(float2*)(o0 + nt * 8) = make_float2(c[nt][0], c[nt][1]);
            *(float2*)(o1 + nt * 8) = make_float2(c[nt][2], c[nt][3]);
        }
    }
}

// =====================================================================
// K2: recurrence (FFMA). Warp owns 2 batch rows; lane owns features
// (lane, lane+32). W_hh rows in regs, h double-buffered in SMEM.
// xp read as scalars (coalesced 128B/lane-row), group-prefetched 4 steps
// ahead. 512 serial steps.
// =====================================================================
__global__ void __launch_bounds__(128, 2) k_rnn(
    const float* __restrict__ h0, const float* __restrict__ Whh,
    float* __restrict__ dout)
{
    __shared__ __align__(16) float sh[4][2][2][HH];  // [warp][row][buf][64]
    const int lane = threadIdx.x & 31;
    const int warp = threadIdx.x >> 5;
    const int gw   = blockIdx.x * 4 + warp;          // 0..1023
    const int b0   = gw * 2;
    const int b1   = gw * 2 + 1;

    u64 w0[32], w1[32];
    {
        const ulonglong2* p0 = (const ulonglong2*)(Whh + (size_t)lane * HH);
        const ulonglong2* p1 = (const ulonglong2*)(Whh + (size_t)(lane + 32) * HH);
#pragma unroll
        for (int k = 0; k < 16; k++) {
            ulonglong2 a = p0[k]; w0[2 * k] = a.x; w0[2 * k + 1] = a.y;
            ulonglong2 b = p1[k]; w1[2 * k] = b.x; w1[2 * k + 1] = b.y;
        }
    }

    float (*shw)[2][HH] = sh[warp];
    shw[0][0][lane]      = h0[(size_t)b0 * HH + lane];
    shw[0][0][lane + 32] = h0[(size_t)b0 * HH + lane + 32];
    shw[1][0][lane]      = h0[(size_t)b1 * HH + lane];
    shw[1][0][lane + 32] = h0[(size_t)b1 * HH + lane + 32];
    __syncwarp();

    const float* xb0 = g_xp + (size_t)b0 * SS * HH;
    const float* xb1 = g_xp + (size_t)b1 * SS * HH;

    float c00[4], c01[4], c10[4], c11[4];
#pragma unroll
    for (int j = 0; j < 4; j++) {
        c00[j] = xb0[j * HH + lane];      c01[j] = xb0[j * HH + lane + 32];
        c10[j] = xb1[j * HH + lane];      c11[j] = xb1[j * HH + lane + 32];
    }

    int buf = 0;
    float v00 = 0.f, v01 = 0.f, v10 = 0.f, v11 = 0.f;

    for (int g = 0; g < 128; g++) {
        float n00[4], n01[4], n10[4], n11[4];
        if (g + 1 < 128) {
#pragma unroll
            for (int j = 0; j < 4; j++) {
                int s = 4 * (g + 1) + j;
                n00[j] = xb0[s * HH + lane];      n01[j] = xb0[s * HH + lane + 32];
                n10[j] = xb1[s * HH + lane];      n11[j] = xb1[s * HH + lane + 32];
            }
        } else {
#pragma unroll
            for (int j = 0; j < 4; j++) { n00[j] = n01[j] = n10[j] = n11[j] = 0.f; }
        }

#pragma unroll
        for (int j = 0; j < 4; j++) {
            const ulonglong2* hp0 = (const ulonglong2*)shw[0][buf];
            const ulonglong2* hp1 = (const ulonglong2*)shw[1][buf];
            u64 a00 = 0, a01 = 0, a10 = 0, a11 = 0;
#pragma unroll
            for (int k = 0; k < 16; k++) {
                ulonglong2 q0 = hp0[k];
                ulonglong2 q1 = hp1[k];
                a00 = ffma2(w0[2*k], q0.x, a00); a00 = ffma2(w0[2*k+1], q0.y, a00);
                a01 = ffma2(w1[2*k], q0.x, a01); a01 = ffma2(w1[2*k+1], q0.y, a01);
                a10 = ffma2(w0[2*k], q1.x, a10); a10 = ffma2(w0[2*k+1], q1.y, a10);
                a11 = ffma2(w1[2*k], q1.x, a11); a11 = ffma2(w1[2*k+1], q1.y, a11);
            }
            float lo, hi;
            upk2(a00, lo, hi); v00 = fmaxf(lo + hi + c00[j], 0.f);
            upk2(a01, lo, hi); v01 = fmaxf(lo + hi + c01[j], 0.f);
            upk2(a10, lo, hi); v10 = fmaxf(lo + hi + c10[j], 0.f);
            upk2(a11, lo, hi); v11 = fmaxf(lo + hi + c11[j], 0.f);

            buf ^= 1;
            shw[0][buf][lane]      = v00;
            shw[0][buf][lane + 32] = v01;
            shw[1][buf][lane]      = v10;
            shw[1][buf][lane + 32] = v11;
            __syncwarp();
        }
#pragma unroll
        for (int j = 0; j < 4; j++) {
            c00[j] = n00[j]; c01[j] = n01[j]; c10[j] = n10[j]; c11[j] = n11[j];
        }
    }

    float* hT = dout + (size_t)BB * OO;
    hT[(size_t)b0 * HH + lane]      = v00;
    hT[(size_t)b0 * HH + lane + 32] = v01;
    hT[(size_t)b1 * HH + lane]      = v10;
    hT[(size_t)b1 * HH + lane + 32] = v11;
}

// =====================================================================
// K3: batchnorm-1 stats, one block per feature, shuffle reduction.
// =====================================================================
__global__ void k_bn1stats(const float* __restrict__ dout,
                           const float* __restrict__ g, const float* __restrict__ bb)
{
    const float* hT = dout + (size_t)BB * OO;
    const int f = blockIdx.x, t = threadIdx.x;
    float s = 0.f, q = 0.f;
    for (int b = t; b < BB; b += 128) {
        float v = hT[(size_t)b * HH + f];
        s += v; q += v * v;
    }
#pragma unroll
    for (int off = 16; off > 0; off >>= 1) {
        s += __shfl_xor_sync(0xffffffffu, s, off);
        q += __shfl_xor_sync(0xffffffffu, q, off);
    }
    __shared__ float ws[4], wq[4];
    if ((t & 31) == 0) { ws[t >> 5] = s; wq[t >> 5] = q; }
    __syncthreads();
    if (t == 0) {
        s = (ws[0] + ws[1]) + (ws[2] + ws[3]);
        q = (wq[0] + wq[1]) + (wq[2] + wq[3]);
        float mu  = s * (1.f / BB);
        float var = q * (1.f / BB) - mu * mu;
        float a   = g[f] * rsqrtf(var + EPSF);
        g_bn1a[f] = a;
        g_bn1c[f] = bb[f] - mu * a;
    }
}

// =====================================================================
// K4: z1 = relu(bn1(hT) @ fc1_W^T + b); bn2 partial stats via shuffles.
// =====================================================================
__global__ void k_fc1(const float* __restrict__ dout,
                      const float* __restrict__ W1, const float* __restrict__ b1f)
{
    const float* hT = dout + (size_t)BB * OO;
    __shared__ float sW[H4 * HH];
    __shared__ float sa[HH], sc[HH], sb[H4];
    __shared__ float wsum[4][H4], wsq[4][H4];
    const int t = threadIdx.x;
    const int lane = t & 31, warp = t >> 5;
    for (int i = t; i < H4 * HH; i += 128) sW[i] = W1[i];
    if (t < HH) { sa[t] = g_bn1a[t]; sc[t] = g_bn1c[t]; }
    if (t < H4) sb[t] = b1f[t];
    __syncthreads();

    const int b = blockIdx.x * 128 + t;
    float y[HH];
    {
        const float4* hp = (const float4*)(hT + (size_t)b * HH);
#pragma unroll
        for (int k = 0; k < 16; k++) {
            float4 u = hp[k];
            y[4*k]   = sa[4*k]   * u.x + sc[4*k];
            y[4*k+1] = sa[4*k+1] * u.y + sc[4*k+1];
            y[4*k+2] = sa[4*k+2] * u.z + sc[4*k+2];
            y[4*k+3] = sa[4*k+3] * u.w + sc[4*k+3];
        }
    }

    float s[H4], q[H4];
    float4* z4 = (float4*)(g_z1 + (size_t)b * H4);
#pragma unroll
    for (int j4 = 0; j4 < 4; j4++) {
        float4 zv;
        float* zp = (float*)&zv;
#pragma unroll
        for (int jj = 0; jj < 4; jj++) {
            int j = j4 * 4 + jj;
            float acc = sb[j];
#pragma unroll
            for (int f = 0; f < HH; f++) acc += sW[j * HH + f] * y[f];
            acc = fmaxf(acc, 0.f);
            zp[jj] = acc;
            s[j] = acc; q[j] = acc * acc;
        }
        z4[j4] = zv;
    }

#pragma unroll
    for (int j = 0; j < H4; j++) {
#pragma unroll
        for (int off = 16; off > 0; off >>= 1) {
            s[j] += __shfl_xor_sync(0xffffffffu, s[j], off);
            q[j] += __shfl_xor_sync(0xffffffffu, q[j], off);
        }
    }
    if (lane == 0) {
#pragma unroll
        for (int j = 0; j < H4; j++) { wsum[warp][j] = s[j]; wsq[warp][j] = q[j]; }
    }
    __syncthreads();
    if (t < H4) {
        g_part[blockIdx.x][0][t] = (wsum[0][t] + wsum[1][t]) + (wsum[2][t] + wsum[3][t]);
        g_part[blockIdx.x][1][t] = (wsq[0][t]  + wsq[1][t])  + (wsq[2][t]  + wsq[3][t]);
    }
}

// =====================================================================
// K5: out = bn2(z1) @ fc2_W^T + b, bn2 coefficients finalized in-block.
// =====================================================================
__global__ void k_fc2(const float* __restrict__ g2, const float* __restrict__ b2,
                      const float* __restrict__ W2, const float* __restrict__ b2f,
                      float* __restrict__ out)
{
    __shared__ float sW[OO * H4], sa[H4], sc[H4], sb[OO];
    const int t = threadIdx.x;
    if (t < H4) {
        float s = 0.f, q = 0.f;
#pragma unroll
        for (int k = 0; k < 16; k++) { s += g_part[k][0][t]; q += g_part[k][1][t]; }
        float mu  = s * (1.f / BB);
        float var = q * (1.f / BB) - mu * mu;
        float a   = g2[t] * rsqrtf(var + EPSF);
        sa[t] = a;
        sc[t] = b2[t] - mu * a;
    }
    sW[t] = W2[t];                 // OO*H4 == 128 == blockDim
    if (t < OO) sb[t] = b2f[t];
    __syncthreads();

    const int b = blockIdx.x * 128 + t;
    float z[H4];
    {
        const float4* zp = (const float4*)(g_z1 + (size_t)b * H4);
#pragma unroll
        for (int k = 0; k < 4; k++) {
            float4 u = zp[k];
            z[4*k]   = sa[4*k]   * u.x + sc[4*k];
            z[4*k+1] = sa[4*k+1] * u.y + sc[4*k+1];
            z[4*k+2] = sa[4*k+2] * u.z + sc[4*k+2];
            z[4*k+3] = sa[4*k+3] * u.w + sc[4*k+3];
        }
    }
#pragma unroll
    for (int o = 0; o < OO; o++) {
        float acc = sb[o];
#pragma unroll
        for (int j = 0; j < H4; j++) acc += sW[o * H4 + j] * z[j];
        out[(size_t)b * OO + o] = acc;
    }
}

// =====================================================================
extern "C" void kernel_launch(void* const* d_in, const int* in_sizes, int n_in,
                              void* d_out, int out_size)
{
    const float* x    = (const float*)d_in[0];
    const float* h0   = (const float*)d_in[1];
    const float* Wih  = (const float*)d_in[2];
    const float* Whh  = (const float*)d_in[3];
    const float* bih  = (const float*)d_in[4];
    const float* bhh  = (const float*)d_in[5];
    const float* bn1g = (const float*)d_in[6];
    const float* bn1b = (const float*)d_in[7];
    const float* fc1W = (const float*)d_in[8];
    const float* fc1b = (const float*)d_in[9];
    const float* bn2g = (const float*)d_in[10];
    const float* bn2b = (const float*)d_in[11];
    const float* fc2W = (const float*)d_in[12];
    const float* fc2b = (const float*)d_in[13];
    float* out = (float*)d_out;

    cudaStream_t s0 = 0;
    k_proj<<<PROJ_BLOCKS, 128, 0, s0>>>(x, Wih, bih, bhh);
    k_rnn<<<256, 128, 0, s0>>>(h0, Whh, out);
    k_bn1stats<<<64, 128, 0, s0>>>(out, bn1g, bn1b);
    k_fc1<<<16, 128, 0, s0>>>(out, fc1W, fc1b);
    k_fc2<<<16, 128, 0, s0>>>(bn2g, bn2b, fc2W, fc2b, out);
}